// round 15
// baseline (speedup 1.0000x reference)
#include <cuda_runtime.h>
#include <cuda_fp16.h>
#include <math.h>

#define NN 331776      // 81 * 4096 nodes
#define NE 4000000     // edges
#define NB 4096        // graphs
#define SLOT 64        // padded-CSR slots per node (max expected deg ~31)

// ---------------- device scratch (static, no allocation) ----------------
__device__ int    g_cur[NN];            // slot counter; after scatter == degree
__device__ float2 g_edge[NN * SLOT];    // padded CSR: {w, bitcast(src)}
__device__ float2 g_Z[NN];              // {ln(sum_pos), ln(sum_neg)}
__device__ float  g_hc[NN * 64];        // fp32: [i*64+0..31]=h1, [32..63]=h2 (head input)
__device__ __half g_h1h[NN * 32];       // fp16 copy of h1 for node2 gathers
__device__ float  g_x[NB * 416];

// ---------------- zero counters ----------------
__global__ void k_zero() {
    int i = blockIdx.x * blockDim.x + threadIdx.x;
    if (i < NN) g_cur[i] = 0;
}

// ---------------- padded scatter: 16 edges/thread ----------------
__global__ void k_scatter(const int* __restrict__ src, const int* __restrict__ dst,
                          const float* __restrict__ w) {
    int t = blockIdx.x * blockDim.x + threadIdx.x;
    if (t >= NE / 16) return;
    const int4*   s4 = reinterpret_cast<const int4*>(src) + 4 * t;
    const int4*   d4 = reinterpret_cast<const int4*>(dst) + 4 * t;
    const float4* w4 = reinterpret_cast<const float4*>(w) + 4 * t;
#pragma unroll
    for (int c = 0; c < 4; c++) {
        int4   s = s4[c];
        int4   d = d4[c];
        float4 ww = w4[c];
        int p0 = atomicAdd(&g_cur[d.x], 1);
        int p1 = atomicAdd(&g_cur[d.y], 1);
        int p2 = atomicAdd(&g_cur[d.z], 1);
        int p3 = atomicAdd(&g_cur[d.w], 1);
        if (p0 < SLOT) g_edge[d.x * SLOT + p0] = make_float2(ww.x, __int_as_float(s.x));
        if (p1 < SLOT) g_edge[d.y * SLOT + p1] = make_float2(ww.y, __int_as_float(s.y));
        if (p2 < SLOT) g_edge[d.z * SLOT + p2] = make_float2(ww.z, __int_as_float(s.z));
        if (p3 < SLOT) g_edge[d.w * SLOT + p3] = make_float2(ww.w, __int_as_float(s.w));
    }
}

// ---------------- layer 1: quad-per-node x 4 nodes/quad, weights hoisted ----------------
// |w| <= ~6 so exp(w) never overflows: no max-subtraction needed.
// The per-lane W1 row-block (24 consecutive floats) + fused bias load ONCE per
// thread and amortize over 4 nodes — kills the ~13 LDG/node epilogue that made
// node1 LSU-issue bound.
__global__ __launch_bounds__(256) void k_node1(
        const float* __restrict__ W1, const float* __restrict__ b1,
        const float* __restrict__ bias1,
        const float* __restrict__ c1s, const float* __restrict__ c1p,
        const float* __restrict__ c1n) {
    int tid = threadIdx.x;
    int q  = tid >> 2;                       // quad id 0..63
    int li = tid & 3;

    // hoisted per-lane constants (uniform across the 4 nodes this quad handles)
    float w1r[24];                           // W1 rows li*8 .. li*8+7 (row-major 3 each)
    {
        const float4* wp = reinterpret_cast<const float4*>(W1 + li * 24);
#pragma unroll
        for (int u = 0; u < 6; u++) reinterpret_cast<float4*>(w1r)[u] = wp[u];
    }
    float bb[8];
    {
        const float4* bp  = reinterpret_cast<const float4*>(b1 + li * 8);
        const float4* bp2 = reinterpret_cast<const float4*>(bias1 + li * 8);
        float4 a0 = bp[0], a1 = bp[1], c0 = bp2[0], c1 = bp2[1];
        bb[0] = a0.x + c0.x; bb[1] = a0.y + c0.y; bb[2] = a0.z + c0.z; bb[3] = a0.w + c0.w;
        bb[4] = a1.x + c1.x; bb[5] = a1.y + c1.y; bb[6] = a1.z + c1.z; bb[7] = a1.w + c1.w;
    }
    float csv = c1s[0], cpv = c1p[0], cnv = c1n[0];

#pragma unroll
    for (int n = 0; n < 4; n++) {
        int i = blockIdx.x * 256 + n * 64 + q;

        int deg = min(g_cur[i], SLOT);
        const float2* ep = &g_edge[(size_t)i * SLOT];

        float sp = 0.f, ap = 0.f, sn = 0.f, an = 0.f;
        for (int b = 4 * li; b < deg; b += 16) {
            float4 q0 = *reinterpret_cast<const float4*>(&ep[b]);       // edges b, b+1
            float4 q1 = *reinterpret_cast<const float4*>(&ep[b + 2]);   // edges b+2, b+3
            {
                float w = q0.x;
                float d = (float)g_cur[__float_as_int(q0.y)];
                float t = __expf(fabsf(w));
                bool p = w > 0.f, ng = w < 0.f;
                sp += p ? t : 0.f;  ap += p ? t * d : 0.f;
                sn += ng ? t : 0.f; an += ng ? t * d : 0.f;
            }
            if (b + 1 < deg) {
                float w = q0.z;
                float d = (float)g_cur[__float_as_int(q0.w)];
                float t = __expf(fabsf(w));
                bool p = w > 0.f, ng = w < 0.f;
                sp += p ? t : 0.f;  ap += p ? t * d : 0.f;
                sn += ng ? t : 0.f; an += ng ? t * d : 0.f;
            }
            if (b + 2 < deg) {
                float w = q1.x;
                float d = (float)g_cur[__float_as_int(q1.y)];
                float t = __expf(fabsf(w));
                bool p = w > 0.f, ng = w < 0.f;
                sp += p ? t : 0.f;  ap += p ? t * d : 0.f;
                sn += ng ? t : 0.f; an += ng ? t * d : 0.f;
            }
            if (b + 3 < deg) {
                float w = q1.z;
                float d = (float)g_cur[__float_as_int(q1.w)];
                float t = __expf(fabsf(w));
                bool p = w > 0.f, ng = w < 0.f;
                sp += p ? t : 0.f;  ap += p ? t * d : 0.f;
                sn += ng ? t : 0.f; an += ng ? t * d : 0.f;
            }
        }
#pragma unroll
        for (int m = 1; m <= 2; m <<= 1) {       // quad reduce
            sp += __shfl_xor_sync(0xffffffffu, sp, m);
            ap += __shfl_xor_sync(0xffffffffu, ap, m);
            sn += __shfl_xor_sync(0xffffffffu, sn, m);
            an += __shfl_xor_sync(0xffffffffu, an, m);
        }
        float rsp = 1.f / fmaxf(sp, 1e-20f), rsn = 1.f / fmaxf(sn, 1e-20f);
        if (li == 0) g_Z[i] = make_float2(-__logf(rsp), -__logf(rsn));

        float c0 = csv * (float)deg;
        float c1 = cpv * (ap * rsp);
        float c2 = cnv * (an * rsn);

        float out[8];
#pragma unroll
        for (int j = 0; j < 8; j++) {
            float v = w1r[j * 3 + 0] * c0 + w1r[j * 3 + 1] * c1 + w1r[j * 3 + 2] * c2
                    + bb[j];
            out[j] = fmaxf(v, 0.f);
        }
        float4* dp = reinterpret_cast<float4*>(&g_hc[(size_t)i * 64 + li * 8]);
        dp[0] = reinterpret_cast<float4*>(out)[0];
        dp[1] = reinterpret_cast<float4*>(out)[1];
        // fp16 copy for layer-2 gathers
        __half2 hh[4];
#pragma unroll
        for (int u = 0; u < 4; u++)
            hh[u] = __float22half2_rn(make_float2(out[2 * u], out[2 * u + 1]));
        *reinterpret_cast<uint4*>(&g_h1h[(size_t)i * 32 + li * 8]) = *reinterpret_cast<uint4*>(hh);
    }
}

// ---------------- layer 2: quad gather + fp16 warp-blocked 8-node GEMV ----------------
__global__ __launch_bounds__(256, 6) void k_node2(
        const float* __restrict__ W2, const float* __restrict__ b2,
        const float* __restrict__ bias2,
        const float* __restrict__ c2s, const float* __restrict__ c2p,
        const float* __restrict__ c2n) {
    __shared__ __half w2h[32 * 104];     // row stride 104 halves (208B): conflict-free uint4
    __shared__ __half combh[8][832];     // per warp: 8 nodes x 104 halves
    int tid = threadIdx.x;
    for (int idx = tid; idx < 3072; idx += 256) {
        int o = idx / 96, k = idx - o * 96;
        w2h[o * 104 + k] = __float2half(W2[idx]);
    }
    __syncthreads();

    int warp = tid >> 5, lane = tid & 31;
    int quad = lane >> 2, li = lane & 3;
    int ibase = blockIdx.x * 64 + warp * 8;
    int i = ibase + quad;                    // this quad's node

    int deg = min(g_cur[i], SLOT);
    float2 Z = g_Z[i];
    const float2* ep = &g_edge[(size_t)i * SLOT];

    float hp[8], hn[8];
#pragma unroll
    for (int j = 0; j < 8; j++) { hp[j] = 0.f; hn[j] = 0.f; }

    int e = 0;
    for (; e + 2 <= deg; e += 2) {           // 2 gather chains in flight
        float2 ev0 = ep[e];
        float2 ev1 = ep[e + 1];
        uint4 r0 = *reinterpret_cast<const uint4*>(
            &g_h1h[(size_t)__float_as_int(ev0.y) * 32 + li * 8]);
        uint4 r1 = *reinterpret_cast<const uint4*>(
            &g_h1h[(size_t)__float_as_int(ev1.y) * 32 + li * 8]);
        {
            float w = ev0.x;
            bool pos = w > 0.f;
            float t = __expf(fabsf(w) - (pos ? Z.x : Z.y));
            float pa = pos ? t : 0.f;
            float na = (w < 0.f) ? t : 0.f;
            const __half2* h2 = reinterpret_cast<const __half2*>(&r0);
#pragma unroll
            for (int q = 0; q < 4; q++) {
                float2 f = __half22float2(h2[q]);
                hp[2 * q]     += pa * f.x;  hp[2 * q + 1] += pa * f.y;
                hn[2 * q]     += na * f.x;  hn[2 * q + 1] += na * f.y;
            }
        }
        {
            float w = ev1.x;
            bool pos = w > 0.f;
            float t = __expf(fabsf(w) - (pos ? Z.x : Z.y));
            float pa = pos ? t : 0.f;
            float na = (w < 0.f) ? t : 0.f;
            const __half2* h2 = reinterpret_cast<const __half2*>(&r1);
#pragma unroll
            for (int q = 0; q < 4; q++) {
                float2 f = __half22float2(h2[q]);
                hp[2 * q]     += pa * f.x;  hp[2 * q + 1] += pa * f.y;
                hn[2 * q]     += na * f.x;  hn[2 * q + 1] += na * f.y;
            }
        }
    }
    if (e < deg) {
        float2 ev = ep[e];
        uint4 r0 = *reinterpret_cast<const uint4*>(
            &g_h1h[(size_t)__float_as_int(ev.y) * 32 + li * 8]);
        float w = ev.x;
        bool pos = w > 0.f;
        float t = __expf(fabsf(w) - (pos ? Z.x : Z.y));
        float pa = pos ? t : 0.f;
        float na = (w < 0.f) ? t : 0.f;
        const __half2* h2 = reinterpret_cast<const __half2*>(&r0);
#pragma unroll
        for (int q = 0; q < 4; q++) {
            float2 f = __half22float2(h2[q]);
            hp[2 * q]     += pa * f.x;  hp[2 * q + 1] += pa * f.y;
            hn[2 * q]     += na * f.x;  hn[2 * q + 1] += na * f.y;
        }
    }

    // Phase B: stage comb (fp16) for this node — quad-partitioned, no reduction
    float csv = c2s[0], cpv = c2p[0], cnv = c2n[0];
    __half* cwh = combh[warp];
    float4 s0 = *reinterpret_cast<const float4*>(&g_hc[(size_t)i * 64 + li * 8]);
    float4 s1 = *reinterpret_cast<const float4*>(&g_hc[(size_t)i * 64 + li * 8 + 4]);
    __half* crow = &cwh[quad * 104];
    {
        __half2 t4[4];
        t4[0] = __float22half2_rn(make_float2(csv * s0.x, csv * s0.y));
        t4[1] = __float22half2_rn(make_float2(csv * s0.z, csv * s0.w));
        t4[2] = __float22half2_rn(make_float2(csv * s1.x, csv * s1.y));
        t4[3] = __float22half2_rn(make_float2(csv * s1.z, csv * s1.w));
        *reinterpret_cast<uint4*>(&crow[li * 8]) = *reinterpret_cast<uint4*>(t4);
        t4[0] = __float22half2_rn(make_float2(cpv * hp[0], cpv * hp[1]));
        t4[1] = __float22half2_rn(make_float2(cpv * hp[2], cpv * hp[3]));
        t4[2] = __float22half2_rn(make_float2(cpv * hp[4], cpv * hp[5]));
        t4[3] = __float22half2_rn(make_float2(cpv * hp[6], cpv * hp[7]));
        *reinterpret_cast<uint4*>(&crow[32 + li * 8]) = *reinterpret_cast<uint4*>(t4);
        t4[0] = __float22half2_rn(make_float2(cnv * hn[0], cnv * hn[1]));
        t4[1] = __float22half2_rn(make_float2(cnv * hn[2], cnv * hn[3]));
        t4[2] = __float22half2_rn(make_float2(cnv * hn[4], cnv * hn[5]));
        t4[3] = __float22half2_rn(make_float2(cnv * hn[6], cnv * hn[7]));
        *reinterpret_cast<uint4*>(&crow[64 + li * 8]) = *reinterpret_cast<uint4*>(t4);
    }
    __syncwarp();

    // Phase C: lane = output feature; 8 nodes register-blocked; fp16 chunks of 8 k
    float bb = b2[lane] + bias2[lane];
    float acc[8];
#pragma unroll
    for (int n = 0; n < 8; n++) acc[n] = bb;
    const __half* wrow = &w2h[lane * 104];
#pragma unroll
    for (int c = 0; c < 12; c++) {
        uint4 wraw = *reinterpret_cast<const uint4*>(&wrow[c * 8]);   // conflict-free
        const __half2* wv = reinterpret_cast<const __half2*>(&wraw);
#pragma unroll
        for (int n = 0; n < 8; n++) {
            uint4 craw = *reinterpret_cast<const uint4*>(&cwh[n * 104 + c * 8]);  // broadcast
            const __half2* cv = reinterpret_cast<const __half2*>(&craw);
            __half2 p = __hmul2(wv[0], cv[0]);
            p = __hfma2(wv[1], cv[1], p);
            p = __hfma2(wv[2], cv[2], p);
            p = __hfma2(wv[3], cv[3], p);
            float2 pf = __half22float2(p);
            acc[n] += pf.x + pf.y;
        }
    }
#pragma unroll
    for (int n = 0; n < 8; n++)
        g_hc[(size_t)(ibase + n) * 64 + 32 + lane] = fmaxf(acc[n], 0.f);
}

// ---------------- head part 1: per-graph conv1 + pairmax + conv2 -> g_x ----------------
__global__ void k_head1(const float* __restrict__ k1, const float* __restrict__ bk1,
                        const float* __restrict__ k2, const float* __restrict__ bk2) {
    __shared__ float feats[80 * 64];
    __shared__ float k1s[16 * 65];
    __shared__ float ps[16 * 40];
    __shared__ float k2s[32 * 49];
    int b = blockIdx.x, tid = threadIdx.x;
    const float4* srcp = reinterpret_cast<const float4*>(&g_hc[(size_t)b * 81 * 64]);
    float4* fp = reinterpret_cast<float4*>(feats);
    for (int idx = tid; idx < 1280; idx += 128) fp[idx] = srcp[idx];
    for (int idx = tid; idx < 1024; idx += 128) {
        int o = idx >> 6, ii = idx & 63;
        k1s[o * 65 + ii] = k1[idx];
    }
    for (int idx = tid; idx < 1536; idx += 128) {
        int c = idx / 48, rem = idx % 48;
        k2s[c * 49 + rem] = k2[idx];
    }
    __syncthreads();

    for (int job = tid; job < 640; job += 128) {
        int o = job & 15, u = job >> 4;
        const float* f0 = &feats[(2 * u) * 64];
        const float* f1 = f0 + 64;
        float a0 = 0.f, a1 = 0.f;
#pragma unroll
        for (int ii = 0; ii < 64; ii++) {
            float wv = k1s[o * 65 + ii];
            a0 += wv * f0[ii];
            a1 += wv * f1[ii];
        }
        float bb = bk1[o];
        ps[o * 40 + u] = fmaxf(a0 + bb, a1 + bb);
    }
    __syncthreads();

    for (int job = tid; job < 416; job += 128) {
        int c = job & 31, jj = job >> 5;
        float acc = bk2[c];
#pragma unroll
        for (int ii = 0; ii < 16; ii++)
#pragma unroll
            for (int r = 0; r < 3; r++)
                acc += k2s[c * 49 + ii * 3 + r] * ps[ii * 40 + 3 * jj + r];
        g_x[b * 416 + c * 13 + jj] = acc;
    }
}

// ---------------- head part 2: FC(416->128) + classifier(10) + log_softmax ----------------
__global__ void k_head2(const float* __restrict__ Wfc, const float* __restrict__ bfc,
                        const float* __restrict__ Wc,  const float* __restrict__ bc,
                        float* __restrict__ out) {
    __shared__ float xs[16 * 416];
    __shared__ float fcs[16 * 128];
    __shared__ float wcs[1280];
    __shared__ float logits[160];
    int blk = blockIdx.x, tid = threadIdx.x;
    int g0 = blk * 16;

    for (int idx = tid; idx < 16 * 416; idx += 128) xs[idx] = g_x[g0 * 416 + idx];
    for (int idx = tid; idx < 1280; idx += 128)     wcs[idx] = Wc[idx];
    __syncthreads();

    {
        float acc[16];
        float bb = bfc[tid];
#pragma unroll
        for (int g = 0; g < 16; g++) acc[g] = bb;
        const float* wr = &Wfc[tid * 416];
        for (int n = 0; n < 416; n++) {
            float wv = wr[n];
#pragma unroll
            for (int g = 0; g < 16; g++) acc[g] += wv * xs[g * 416 + n];
        }
#pragma unroll
        for (int g = 0; g < 16; g++) fcs[g * 128 + tid] = fmaxf(acc[g], 0.f);
    }
    __syncthreads();

    for (int job = tid; job < 160; job += 128) {
        int g = job / 10, c = job % 10;
        float acc = bc[c];
#pragma unroll
        for (int k = 0; k < 128; k++) acc += wcs[c * 128 + k] * fcs[g * 128 + k];
        logits[g * 10 + c] = acc;
    }
    __syncthreads();

    if (tid < 16) {
        float m = -1e30f;
        for (int c = 0; c < 10; c++) m = fmaxf(m, logits[tid * 10 + c]);
        float s = 0.f;
        for (int c = 0; c < 10; c++) s += __expf(logits[tid * 10 + c] - m);
        float ls = logf(s) + m;
        for (int c = 0; c < 10; c++)
            out[(g0 + tid) * 10 + c] = logits[tid * 10 + c] - ls;
    }
}

// ---------------- launch ----------------
extern "C" void kernel_launch(void* const* d_in, const int* in_sizes, int n_in,
                              void* d_out, int out_size) {
    const int*   src = (const int*)d_in[0];
    const int*   dst = (const int*)d_in[1];
    const float* w   = (const float*)d_in[2];
    int p = (in_sizes[3] == 96) ? 3 : 4;   // skip n_nodes scalar if present
    const float* W1    = (const float*)d_in[p + 0];
    const float* b1    = (const float*)d_in[p + 1];
    const float* bias1 = (const float*)d_in[p + 2];
    const float* c1s   = (const float*)d_in[p + 3];
    const float* c1p   = (const float*)d_in[p + 4];
    const float* c1n   = (const float*)d_in[p + 5];
    const float* W2    = (const float*)d_in[p + 6];
    const float* b2    = (const float*)d_in[p + 7];
    const float* bias2 = (const float*)d_in[p + 8];
    const float* c2s   = (const float*)d_in[p + 9];
    const float* c2p   = (const float*)d_in[p + 10];
    const float* c2n   = (const float*)d_in[p + 11];
    const float* k1    = (const float*)d_in[p + 12];
    const float* bk1   = (const float*)d_in[p + 13];
    const float* k2    = (const float*)d_in[p + 14];
    const float* bk2   = (const float*)d_in[p + 15];
    const float* Wfc   = (const float*)d_in[p + 16];
    const float* bfc   = (const float*)d_in[p + 17];
    const float* Wc    = (const float*)d_in[p + 18];
    const float* bc    = (const float*)d_in[p + 19];
    float* out = (float*)d_out;

    k_zero   <<<(NN + 1023) / 1024, 1024>>>();
    k_scatter<<<(NE / 16 + 255) / 256, 256>>>(src, dst, w);
    k_node1  <<<NN / 256, 256>>>(W1, b1, bias1, c1s, c1p, c1n);
    k_node2  <<<NN / 64, 256>>>(W2, b2, bias2, c2s, c2p, c2n);
    k_head1  <<<NB, 128>>>(k1, bk1, k2, bk2);
    k_head2  <<<NB / 16, 128>>>(Wfc, bfc, Wc, bc, out);
}

// round 16
// speedup vs baseline: 1.0905x; 1.0905x over previous
#include <cuda_runtime.h>
#include <cuda_fp16.h>
#include <math.h>

#define NN 331776      // 81 * 4096 nodes
#define NE 4000000     // edges
#define NB 4096        // graphs
#define SLOT 64        // padded-CSR slots per node (max expected deg ~31)

// ---------------- device scratch (static, no allocation) ----------------
__device__ int    g_cur[NN];            // slot counter; after scatter == degree
__device__ float2 g_edge[NN * SLOT];    // padded CSR: {w, bitcast(src)}
__device__ float2 g_Z[NN];              // {ln(sum_pos), ln(sum_neg)}
__device__ float  g_hc[NN * 64];        // fp32: [i*64+0..31]=h1, [32..63]=h2 (head input)
__device__ __half g_h1h[NN * 32];       // fp16 copy of h1 for node2 gathers
__device__ float  g_x[NB * 416];

// ---------------- zero counters ----------------
__global__ void k_zero() {
    int i = blockIdx.x * blockDim.x + threadIdx.x;
    if (i < NN) g_cur[i] = 0;
}

// ---------------- padded scatter: 16 edges/thread ----------------
__global__ void k_scatter(const int* __restrict__ src, const int* __restrict__ dst,
                          const float* __restrict__ w) {
    int t = blockIdx.x * blockDim.x + threadIdx.x;
    if (t >= NE / 16) return;
    const int4*   s4 = reinterpret_cast<const int4*>(src) + 4 * t;
    const int4*   d4 = reinterpret_cast<const int4*>(dst) + 4 * t;
    const float4* w4 = reinterpret_cast<const float4*>(w) + 4 * t;
#pragma unroll
    for (int c = 0; c < 4; c++) {
        int4   s = s4[c];
        int4   d = d4[c];
        float4 ww = w4[c];
        int p0 = atomicAdd(&g_cur[d.x], 1);
        int p1 = atomicAdd(&g_cur[d.y], 1);
        int p2 = atomicAdd(&g_cur[d.z], 1);
        int p3 = atomicAdd(&g_cur[d.w], 1);
        if (p0 < SLOT) g_edge[d.x * SLOT + p0] = make_float2(ww.x, __int_as_float(s.x));
        if (p1 < SLOT) g_edge[d.y * SLOT + p1] = make_float2(ww.y, __int_as_float(s.y));
        if (p2 < SLOT) g_edge[d.z * SLOT + p2] = make_float2(ww.z, __int_as_float(s.z));
        if (p3 < SLOT) g_edge[d.w * SLOT + p3] = make_float2(ww.w, __int_as_float(s.w));
    }
}

// ---------------- layer 1: quad-per-node, 4 edges (2 float4) per lane-iter ----------------
// (R14 version — the R15 4-node variant was neutral and is reverted)
__global__ __launch_bounds__(256) void k_node1(
        const float* __restrict__ W1, const float* __restrict__ b1,
        const float* __restrict__ bias1,
        const float* __restrict__ c1s, const float* __restrict__ c1p,
        const float* __restrict__ c1n) {
    int tid = threadIdx.x;
    int i  = blockIdx.x * 64 + (tid >> 2);   // 64 nodes per 256-thread block
    int li = tid & 3;

    int deg = min(g_cur[i], SLOT);
    const float2* ep = &g_edge[(size_t)i * SLOT];

    float sp = 0.f, ap = 0.f, sn = 0.f, an = 0.f;
    for (int b = 4 * li; b < deg; b += 16) {
        float4 q0 = *reinterpret_cast<const float4*>(&ep[b]);       // edges b, b+1
        float4 q1 = *reinterpret_cast<const float4*>(&ep[b + 2]);   // edges b+2, b+3
        {
            float w = q0.x;
            float d = (float)g_cur[__float_as_int(q0.y)];
            float t = __expf(fabsf(w));
            bool p = w > 0.f, n = w < 0.f;
            sp += p ? t : 0.f;  ap += p ? t * d : 0.f;
            sn += n ? t : 0.f;  an += n ? t * d : 0.f;
        }
        if (b + 1 < deg) {
            float w = q0.z;
            float d = (float)g_cur[__float_as_int(q0.w)];
            float t = __expf(fabsf(w));
            bool p = w > 0.f, n = w < 0.f;
            sp += p ? t : 0.f;  ap += p ? t * d : 0.f;
            sn += n ? t : 0.f;  an += n ? t * d : 0.f;
        }
        if (b + 2 < deg) {
            float w = q1.x;
            float d = (float)g_cur[__float_as_int(q1.y)];
            float t = __expf(fabsf(w));
            bool p = w > 0.f, n = w < 0.f;
            sp += p ? t : 0.f;  ap += p ? t * d : 0.f;
            sn += n ? t : 0.f;  an += n ? t * d : 0.f;
        }
        if (b + 3 < deg) {
            float w = q1.z;
            float d = (float)g_cur[__float_as_int(q1.w)];
            float t = __expf(fabsf(w));
            bool p = w > 0.f, n = w < 0.f;
            sp += p ? t : 0.f;  ap += p ? t * d : 0.f;
            sn += n ? t : 0.f;  an += n ? t * d : 0.f;
        }
    }
#pragma unroll
    for (int m = 1; m <= 2; m <<= 1) {       // quad reduce
        sp += __shfl_xor_sync(0xffffffffu, sp, m);
        ap += __shfl_xor_sync(0xffffffffu, ap, m);
        sn += __shfl_xor_sync(0xffffffffu, sn, m);
        an += __shfl_xor_sync(0xffffffffu, an, m);
    }
    float rsp = 1.f / fmaxf(sp, 1e-20f), rsn = 1.f / fmaxf(sn, 1e-20f);
    if (li == 0) g_Z[i] = make_float2(-__logf(rsp), -__logf(rsn));

    float c0 = c1s[0] * (float)deg;
    float c1 = c1p[0] * (ap * rsp);
    float c2 = c1n[0] * (an * rsn);

    float out[8];
#pragma unroll
    for (int j = 0; j < 8; j++) {
        int o = li * 8 + j;
        float v = W1[o * 3 + 0] * c0 + W1[o * 3 + 1] * c1 + W1[o * 3 + 2] * c2
                + b1[o] + bias1[o];
        out[j] = fmaxf(v, 0.f);
    }
    float4* dp = reinterpret_cast<float4*>(&g_hc[(size_t)i * 64 + li * 8]);
    dp[0] = reinterpret_cast<float4*>(out)[0];
    dp[1] = reinterpret_cast<float4*>(out)[1];
    // fp16 copy for layer-2 gathers
    __half2 hh[4];
#pragma unroll
    for (int q = 0; q < 4; q++)
        hh[q] = __float22half2_rn(make_float2(out[2 * q], out[2 * q + 1]));
    *reinterpret_cast<uint4*>(&g_h1h[(size_t)i * 32 + li * 8]) = *reinterpret_cast<uint4*>(hh);
}

// ---------------- layer 2: quad gather + fp16 warp-blocked 8-node GEMV ----------------
__global__ __launch_bounds__(256, 6) void k_node2(
        const float* __restrict__ W2, const float* __restrict__ b2,
        const float* __restrict__ bias2,
        const float* __restrict__ c2s, const float* __restrict__ c2p,
        const float* __restrict__ c2n) {
    __shared__ __half w2h[32 * 104];     // row stride 104 halves (208B): conflict-free uint4
    __shared__ __half combh[8][832];     // per warp: 8 nodes x 104 halves
    int tid = threadIdx.x;
    for (int idx = tid; idx < 3072; idx += 256) {
        int o = idx / 96, k = idx - o * 96;
        w2h[o * 104 + k] = __float2half(W2[idx]);
    }
    __syncthreads();

    int warp = tid >> 5, lane = tid & 31;
    int quad = lane >> 2, li = lane & 3;
    int ibase = blockIdx.x * 64 + warp * 8;
    int i = ibase + quad;                    // this quad's node

    int deg = min(g_cur[i], SLOT);
    float2 Z = g_Z[i];
    const float2* ep = &g_edge[(size_t)i * SLOT];

    float hp[8], hn[8];
#pragma unroll
    for (int j = 0; j < 8; j++) { hp[j] = 0.f; hn[j] = 0.f; }

    int e = 0;
    for (; e + 2 <= deg; e += 2) {           // 2 gather chains in flight
        float2 ev0 = ep[e];
        float2 ev1 = ep[e + 1];
        uint4 r0 = *reinterpret_cast<const uint4*>(
            &g_h1h[(size_t)__float_as_int(ev0.y) * 32 + li * 8]);
        uint4 r1 = *reinterpret_cast<const uint4*>(
            &g_h1h[(size_t)__float_as_int(ev1.y) * 32 + li * 8]);
        {
            float w = ev0.x;
            bool pos = w > 0.f;
            float t = __expf(fabsf(w) - (pos ? Z.x : Z.y));
            float pa = pos ? t : 0.f;
            float na = (w < 0.f) ? t : 0.f;
            const __half2* h2 = reinterpret_cast<const __half2*>(&r0);
#pragma unroll
            for (int q = 0; q < 4; q++) {
                float2 f = __half22float2(h2[q]);
                hp[2 * q]     += pa * f.x;  hp[2 * q + 1] += pa * f.y;
                hn[2 * q]     += na * f.x;  hn[2 * q + 1] += na * f.y;
            }
        }
        {
            float w = ev1.x;
            bool pos = w > 0.f;
            float t = __expf(fabsf(w) - (pos ? Z.x : Z.y));
            float pa = pos ? t : 0.f;
            float na = (w < 0.f) ? t : 0.f;
            const __half2* h2 = reinterpret_cast<const __half2*>(&r1);
#pragma unroll
            for (int q = 0; q < 4; q++) {
                float2 f = __half22float2(h2[q]);
                hp[2 * q]     += pa * f.x;  hp[2 * q + 1] += pa * f.y;
                hn[2 * q]     += na * f.x;  hn[2 * q + 1] += na * f.y;
            }
        }
    }
    if (e < deg) {
        float2 ev = ep[e];
        uint4 r0 = *reinterpret_cast<const uint4*>(
            &g_h1h[(size_t)__float_as_int(ev.y) * 32 + li * 8]);
        float w = ev.x;
        bool pos = w > 0.f;
        float t = __expf(fabsf(w) - (pos ? Z.x : Z.y));
        float pa = pos ? t : 0.f;
        float na = (w < 0.f) ? t : 0.f;
        const __half2* h2 = reinterpret_cast<const __half2*>(&r0);
#pragma unroll
        for (int q = 0; q < 4; q++) {
            float2 f = __half22float2(h2[q]);
            hp[2 * q]     += pa * f.x;  hp[2 * q + 1] += pa * f.y;
            hn[2 * q]     += na * f.x;  hn[2 * q + 1] += na * f.y;
        }
    }

    // Phase B: stage comb (fp16) for this node — quad-partitioned, no reduction
    float csv = c2s[0], cpv = c2p[0], cnv = c2n[0];
    __half* cwh = combh[warp];
    float4 s0 = *reinterpret_cast<const float4*>(&g_hc[(size_t)i * 64 + li * 8]);
    float4 s1 = *reinterpret_cast<const float4*>(&g_hc[(size_t)i * 64 + li * 8 + 4]);
    __half* crow = &cwh[quad * 104];
    {
        __half2 t4[4];
        t4[0] = __float22half2_rn(make_float2(csv * s0.x, csv * s0.y));
        t4[1] = __float22half2_rn(make_float2(csv * s0.z, csv * s0.w));
        t4[2] = __float22half2_rn(make_float2(csv * s1.x, csv * s1.y));
        t4[3] = __float22half2_rn(make_float2(csv * s1.z, csv * s1.w));
        *reinterpret_cast<uint4*>(&crow[li * 8]) = *reinterpret_cast<uint4*>(t4);
        t4[0] = __float22half2_rn(make_float2(cpv * hp[0], cpv * hp[1]));
        t4[1] = __float22half2_rn(make_float2(cpv * hp[2], cpv * hp[3]));
        t4[2] = __float22half2_rn(make_float2(cpv * hp[4], cpv * hp[5]));
        t4[3] = __float22half2_rn(make_float2(cpv * hp[6], cpv * hp[7]));
        *reinterpret_cast<uint4*>(&crow[32 + li * 8]) = *reinterpret_cast<uint4*>(t4);
        t4[0] = __float22half2_rn(make_float2(cnv * hn[0], cnv * hn[1]));
        t4[1] = __float22half2_rn(make_float2(cnv * hn[2], cnv * hn[3]));
        t4[2] = __float22half2_rn(make_float2(cnv * hn[4], cnv * hn[5]));
        t4[3] = __float22half2_rn(make_float2(cnv * hn[6], cnv * hn[7]));
        *reinterpret_cast<uint4*>(&crow[64 + li * 8]) = *reinterpret_cast<uint4*>(t4);
    }
    __syncwarp();

    // Phase C: lane = output feature; 8 nodes register-blocked; fp16 chunks of 8 k
    float bb = b2[lane] + bias2[lane];
    float acc[8];
#pragma unroll
    for (int n = 0; n < 8; n++) acc[n] = bb;
    const __half* wrow = &w2h[lane * 104];
#pragma unroll
    for (int c = 0; c < 12; c++) {
        uint4 wraw = *reinterpret_cast<const uint4*>(&wrow[c * 8]);   // conflict-free
        const __half2* wv = reinterpret_cast<const __half2*>(&wraw);
#pragma unroll
        for (int n = 0; n < 8; n++) {
            uint4 craw = *reinterpret_cast<const uint4*>(&cwh[n * 104 + c * 8]);  // broadcast
            const __half2* cv = reinterpret_cast<const __half2*>(&craw);
            __half2 p = __hmul2(wv[0], cv[0]);
            p = __hfma2(wv[1], cv[1], p);
            p = __hfma2(wv[2], cv[2], p);
            p = __hfma2(wv[3], cv[3], p);
            float2 pf = __half22float2(p);
            acc[n] += pf.x + pf.y;
        }
    }
#pragma unroll
    for (int n = 0; n < 8; n++)
        g_hc[(size_t)(ibase + n) * 64 + 32 + lane] = fmaxf(acc[n], 0.f);
}

// ---------------- head part 1: float4 conv1 + register-hoisted conv2 ----------------
__global__ void k_head1(const float* __restrict__ k1, const float* __restrict__ bk1,
                        const float* __restrict__ k2, const float* __restrict__ bk2) {
    __shared__ float feats[80 * 64];
    __shared__ float k1s[16 * 68];     // stride 68 floats for float4 access
    __shared__ float ps[16 * 40];
    int b = blockIdx.x, tid = threadIdx.x;
    const float4* srcp = reinterpret_cast<const float4*>(&g_hc[(size_t)b * 81 * 64]);
    float4* fp = reinterpret_cast<float4*>(feats);
    for (int idx = tid; idx < 1280; idx += 128) fp[idx] = srcp[idx];
    for (int idx = tid; idx < 1024; idx += 128) {
        int o = idx >> 6, ii = idx & 63;
        k1s[o * 68 + ii] = k1[idx];
    }
    // hoist this thread's k2 row (c = tid & 31 is constant across its conv2 jobs)
    float k2r[48];
    {
        int c = tid & 31;
        const float4* kp = reinterpret_cast<const float4*>(k2 + c * 48);
#pragma unroll
        for (int u = 0; u < 12; u++) reinterpret_cast<float4*>(k2r)[u] = kp[u];
    }
    __syncthreads();

    // conv1 (dot-64) + bias + pair max, vectorized float4
    for (int job = tid; job < 640; job += 128) {
        int o = job & 15, u = job >> 4;
        const float4* f0 = reinterpret_cast<const float4*>(&feats[(2 * u) * 64]);
        const float4* f1 = f0 + 16;
        const float4* kv = reinterpret_cast<const float4*>(&k1s[o * 68]);
        float a0 = 0.f, a1 = 0.f;
#pragma unroll
        for (int ii = 0; ii < 16; ii++) {
            float4 k4 = kv[ii];
            float4 v0 = f0[ii];
            float4 v1 = f1[ii];
            a0 += k4.x * v0.x + k4.y * v0.y + k4.z * v0.z + k4.w * v0.w;
            a1 += k4.x * v1.x + k4.y * v1.y + k4.z * v1.z + k4.w * v1.w;
        }
        float bb = bk1[o];
        ps[o * 40 + u] = fmaxf(a0 + bb, a1 + bb);
    }
    __syncthreads();

    // conv2 (32,16,3) stride 3 -> (32,13); k2 row in registers, ps broadcast LDS
    for (int job = tid; job < 416; job += 128) {
        int c = job & 31, jj = job >> 5;
        float acc = bk2[c];
#pragma unroll
        for (int ii = 0; ii < 16; ii++) {
            acc += k2r[ii * 3 + 0] * ps[ii * 40 + 3 * jj + 0];
            acc += k2r[ii * 3 + 1] * ps[ii * 40 + 3 * jj + 1];
            acc += k2r[ii * 3 + 2] * ps[ii * 40 + 3 * jj + 2];
        }
        g_x[b * 416 + c * 13 + jj] = acc;
    }
}

// ---------------- head part 2: 8 graphs/block, float4 FC + classifier + log_softmax ----------------
__global__ void k_head2(const float* __restrict__ Wfc, const float* __restrict__ bfc,
                        const float* __restrict__ Wc,  const float* __restrict__ bc,
                        float* __restrict__ out) {
    __shared__ float xs[8 * 416];
    __shared__ float fcs[8 * 128];
    __shared__ float wcs[1280];
    __shared__ float logits[80];
    int blk = blockIdx.x, tid = threadIdx.x;
    int g0 = blk * 8;

    {
        const float4* gp = reinterpret_cast<const float4*>(&g_x[g0 * 416]);
        float4* xp = reinterpret_cast<float4*>(xs);
        for (int idx = tid; idx < 8 * 104; idx += 128) xp[idx] = gp[idx];
    }
    for (int idx = tid; idx < 1280; idx += 128) wcs[idx] = Wc[idx];
    __syncthreads();

    // thread = output feature f; 8 graphs register-blocked; float4 loads
    {
        float acc[8];
        float bb = bfc[tid];
#pragma unroll
        for (int g = 0; g < 8; g++) acc[g] = bb;
        const float4* wr = reinterpret_cast<const float4*>(&Wfc[tid * 416]);
        for (int n4 = 0; n4 < 104; n4++) {
            float4 wv = wr[n4];
#pragma unroll
            for (int g = 0; g < 8; g++) {
                float4 xv = *reinterpret_cast<const float4*>(&xs[g * 416 + n4 * 4]); // broadcast
                acc[g] += wv.x * xv.x + wv.y * xv.y + wv.z * xv.z + wv.w * xv.w;
            }
        }
#pragma unroll
        for (int g = 0; g < 8; g++) fcs[g * 128 + tid] = fmaxf(acc[g], 0.f);
    }
    __syncthreads();

    for (int job = tid; job < 80; job += 128) {
        int g = job / 10, c = job % 10;
        float acc = bc[c];
#pragma unroll
        for (int k = 0; k < 128; k += 4) {
            float4 wv = *reinterpret_cast<const float4*>(&wcs[c * 128 + k]);
            float4 fv = *reinterpret_cast<const float4*>(&fcs[g * 128 + k]);
            acc += wv.x * fv.x + wv.y * fv.y + wv.z * fv.z + wv.w * fv.w;
        }
        logits[g * 10 + c] = acc;
    }
    __syncthreads();

    if (tid < 8) {
        float m = -1e30f;
        for (int c = 0; c < 10; c++) m = fmaxf(m, logits[tid * 10 + c]);
        float s = 0.f;
        for (int c = 0; c < 10; c++) s += __expf(logits[tid * 10 + c] - m);
        float ls = logf(s) + m;
        for (int c = 0; c < 10; c++)
            out[(g0 + tid) * 10 + c] = logits[tid * 10 + c] - ls;
    }
}

// ---------------- launch ----------------
extern "C" void kernel_launch(void* const* d_in, const int* in_sizes, int n_in,
                              void* d_out, int out_size) {
    const int*   src = (const int*)d_in[0];
    const int*   dst = (const int*)d_in[1];
    const float* w   = (const float*)d_in[2];
    int p = (in_sizes[3] == 96) ? 3 : 4;   // skip n_nodes scalar if present
    const float* W1    = (const float*)d_in[p + 0];
    const float* b1    = (const float*)d_in[p + 1];
    const float* bias1 = (const float*)d_in[p + 2];
    const float* c1s   = (const float*)d_in[p + 3];
    const float* c1p   = (const float*)d_in[p + 4];
    const float* c1n   = (const float*)d_in[p + 5];
    const float* W2    = (const float*)d_in[p + 6];
    const float* b2    = (const float*)d_in[p + 7];
    const float* bias2 = (const float*)d_in[p + 8];
    const float* c2s   = (const float*)d_in[p + 9];
    const float* c2p   = (const float*)d_in[p + 10];
    const float* c2n   = (const float*)d_in[p + 11];
    const float* k1    = (const float*)d_in[p + 12];
    const float* bk1   = (const float*)d_in[p + 13];
    const float* k2    = (const float*)d_in[p + 14];
    const float* bk2   = (const float*)d_in[p + 15];
    const float* Wfc   = (const float*)d_in[p + 16];
    const float* bfc   = (const float*)d_in[p + 17];
    const float* Wc    = (const float*)d_in[p + 18];
    const float* bc    = (const float*)d_in[p + 19];
    float* out = (float*)d_out;

    k_zero   <<<(NN + 1023) / 1024, 1024>>>();
    k_scatter<<<(NE / 16 + 255) / 256, 256>>>(src, dst, w);
    k_node1  <<<NN / 64, 256>>>(W1, b1, bias1, c1s, c1p, c1n);
    k_node2  <<<NN / 64, 256>>>(W2, b2, bias2, c2s, c2p, c2n);
    k_head1  <<<NB, 128>>>(k1, bk1, k2, bk2);
    k_head2  <<<NB / 8, 128>>>(Wfc, bfc, Wc, bc, out);
}